// round 11
// baseline (speedup 1.0000x reference)
#include <cuda_runtime.h>
#include <cuda_fp16.h>
#include <cstdint>
#include <cstddef>

#define DI __device__ __forceinline__

static constexpr int Mdim = 8192, Ndim = 4096, Kdim = 4096;
static constexpr int MT = 128, NT = 128, KT = 64;
static constexpr int NKT = Kdim / KT;              // 64
static constexpr int ROWB = 160;                   // row stride bytes (128B data + 32B pad)
static constexpr int RP8 = ROWB / 8;               // 20
static constexpr int TILE_A = 128 * ROWB;          // 20480 B
static constexpr int TILE_B = 128 * ROWB;          // 20480 B
static constexpr int STG = TILE_A + TILE_B;        // 40960 B
static constexpr unsigned SMEM_BYTES = 2 * STG;    // 81920 (x2 CTAs = 160KB/SM)

// fp16, k-interleaved within each 16-k group: word slots [k0k1 k8k9 k2k3 k10k11 k4k5 k12k13 k6k7 k14k15]
__device__ __half g_wt[(size_t)Ndim * Kdim];       // W^T [n][k]
__device__ __half g_a [(size_t)Mdim * Kdim];       // A   [m][k]

DI uint32_t smem_u32(const void* p) {
    uint32_t a;
    asm("{ .reg .u64 t; cvta.to.shared.u64 t, %1; cvt.u32.u64 %0, t; }" : "=r"(a) : "l"(p));
    return a;
}
DI void cpa16(uint32_t dst, const void* src) {
    asm volatile("cp.async.cg.shared.global [%0], [%1], 16;" :: "r"(dst), "l"(src) : "memory");
}
DI void cpa_commit() { asm volatile("cp.async.commit_group;" ::: "memory"); }
template <int N> DI void cpa_wait() {
    asm volatile("cp.async.wait_group %0;" :: "n"(N) : "memory");
}
DI void mma16(float* d, uint32_t a0, uint32_t a1, uint32_t a2, uint32_t a3,
              uint32_t b0, uint32_t b1) {
    asm volatile(
        "mma.sync.aligned.m16n8k16.row.col.f32.f16.f16.f32 "
        "{%0,%1,%2,%3}, {%4,%5,%6,%7}, {%8,%9}, {%0,%1,%2,%3};"
        : "+f"(d[0]), "+f"(d[1]), "+f"(d[2]), "+f"(d[3])
        : "r"(a0), "r"(a1), "r"(a2), "r"(a3), "r"(b0), "r"(b1));
}
DI int ileave16(int e) {
    int p = (e >> 1) & 7, o = e & 1;
    int slot = ((p & 3) << 1) | (p >> 2);
    return (e & ~15) | (slot << 1) | o;
}

// ---------- prep 1: g_wt[n][ik] = fp16(q[k][n]*s[k][n/32]), transposed + interleaved ----------
__global__ void dequant_k(const int* __restrict__ q, const float* __restrict__ s) {
    __shared__ float t[32][33];
    int n0 = blockIdx.x * 32, k0 = blockIdx.y * 32;
    int tx = threadIdx.x, ty = threadIdx.y;   // 32 x 8
    int sb = n0 >> 5;
#pragma unroll
    for (int i = 0; i < 4; i++) {
        int k = k0 + ty + i * 8;
        t[ty + i * 8][tx] = (float)q[(size_t)k * Ndim + n0 + tx] * s[(size_t)k * (Ndim / 32) + sb];
    }
    __syncthreads();
    int itx = ileave16(tx);
#pragma unroll
    for (int i = 0; i < 4; i++)
        g_wt[(size_t)(n0 + ty + i * 8) * Kdim + k0 + itx] = __float2half_rn(t[tx][ty + i * 8]);
}

// ---------- prep 2: A f32 -> fp16 + interleave (one 16-k group per thread) ----------
__global__ void round_a_k(const float* __restrict__ in) {
    size_t idx = (size_t)blockIdx.x * blockDim.x + threadIdx.x;  // M*K/16
    size_t m = idx >> 8;                   // K/16 = 256 groups per row
    int g = (int)(idx & 255);
    const float* p = in + m * Kdim + g * 16;
    uint32_t w[8];
#pragma unroll
    for (int s = 0; s < 8; s++) {
        int pp = (s >> 1) + ((s & 1) << 2);
        __half2 h = __floats2half2_rn(p[2 * pp], p[2 * pp + 1]);
        w[s] = *reinterpret_cast<uint32_t*>(&h);
    }
    uint4* dst = reinterpret_cast<uint4*>(g_a + m * Kdim + g * 16);
    dst[0] = make_uint4(w[0], w[1], w[2], w[3]);
    dst[1] = make_uint4(w[4], w[5], w[6], w[7]);
}

// ---------- GEMM: fp16 m16n8k16, 128x128x64 CTA, 256 thr, warp 64x32, 2 CTA/SM ----------
DI void load_tile(uint32_t sb, int tid, int m0, int n0, int jt, int s) {
    const __half* Ap = g_a  + (size_t)m0 * Kdim + jt * KT;
    const __half* Bp = g_wt + (size_t)n0 * Kdim + jt * KT;
    uint32_t base = sb + (uint32_t)s * STG;
#pragma unroll
    for (int i = 0; i < 8; i++) {
        int idx = tid + i * 256;                 // 0..2047
        int half = idx >> 10;                    // 0 = A, 1 = B
        int j = idx & 1023;
        int r = j >> 3, c = j & 7;               // row 0..127, 16B chunk 0..7
        const __half* src = (half ? Bp : Ap) + (size_t)r * Kdim + c * 8;
        cpa16(base + (uint32_t)half * TILE_A + (uint32_t)(r * ROWB + c * 16), src);
    }
    cpa_commit();
}

__global__ void __launch_bounds__(256, 2) gemm_k(const float* __restrict__ bias,
                                                 float* __restrict__ out) {
    extern __shared__ __align__(1024) char smem[];
    uint32_t sb = smem_u32(smem);
    int tid = threadIdx.x, wid = tid >> 5, lane = tid & 31;
    int qr = lane >> 2, qt = lane & 3;
    int wm = wid >> 2, wn = wid & 3;            // 2 x 4 warp grid, 64x32 warp tile
    int n0 = blockIdx.x * NT, m0 = blockIdx.y * MT;
    int rA = wm * 64 + qr;
    int rB = wn * 32 + qr;

    float acc[4][4][4];
#pragma unroll
    for (int a = 0; a < 4; a++)
#pragma unroll
        for (int b = 0; b < 4; b++)
#pragma unroll
            for (int c = 0; c < 4; c++) acc[a][b][c] = 0.f;

    load_tile(sb, tid, m0, n0, 0, 0);

    for (int jt = 0; jt < NKT; ++jt) {
        cpa_wait<0>();                          // tile jt resident
        __syncthreads();                        // everyone done with the other stage
        if (jt + 1 < NKT)                       // prefetch next into the freed stage
            load_tile(sb, tid, m0, n0, jt + 1, (jt + 1) & 1);

        int s = jt & 1;
        const uint2* As2 = (const uint2*)(smem + (size_t)s * STG) + (size_t)rA * RP8;
        const uint2* Bs2 = (const uint2*)(smem + (size_t)s * STG + TILE_A) + (size_t)rB * RP8;

#pragma unroll
        for (int ks = 0; ks < 4; ++ks) {
            int co = ks * 4 + qt;
            uint2 a02[4], a13[4], bb[4];
#pragma unroll
            for (int mi = 0; mi < 4; ++mi) {
                a02[mi] = As2[(mi * 16)     * RP8 + co];
                a13[mi] = As2[(mi * 16 + 8) * RP8 + co];
            }
#pragma unroll
            for (int ni = 0; ni < 4; ++ni)
                bb[ni] = Bs2[(ni * 8) * RP8 + co];
#pragma unroll
            for (int mi = 0; mi < 4; ++mi)
#pragma unroll
                for (int ni = 0; ni < 4; ++ni)
                    mma16(acc[mi][ni], a02[mi].x, a13[mi].x, a02[mi].y, a13[mi].y,
                          bb[ni].x, bb[ni].y);
        }
        __syncthreads();                        // readers done before next overwrite
    }

#pragma unroll
    for (int mi = 0; mi < 4; ++mi) {
        int r0 = m0 + wm * 64 + mi * 16 + qr;
#pragma unroll
        for (int ni = 0; ni < 4; ++ni) {
            int n = n0 + wn * 32 + ni * 8 + 2 * qt;
            float b0 = bias[n], b1 = bias[n + 1];
            float2 v0 = {acc[mi][ni][0] + b0, acc[mi][ni][1] + b1};
            float2 v1 = {acc[mi][ni][2] + b0, acc[mi][ni][3] + b1};
            *reinterpret_cast<float2*>(out + (size_t)r0 * Ndim + n) = v0;
            *reinterpret_cast<float2*>(out + (size_t)(r0 + 8) * Ndim + n) = v1;
        }
    }
}

extern "C" void kernel_launch(void* const* d_in, const int* in_sizes, int n_in,
                              void* d_out, int out_size) {
    const float* inp  = (const float*)d_in[0];
    const int*   qw   = (const int*)d_in[1];
    const float* sc   = (const float*)d_in[2];
    const float* bias = (const float*)d_in[3];
    float* out = (float*)d_out;

    cudaFuncSetAttribute(gemm_k, cudaFuncAttributeMaxDynamicSharedMemorySize, SMEM_BYTES);

    dequant_k<<<dim3(Ndim / 32, Kdim / 32), dim3(32, 8)>>>(qw, sc);
    round_a_k<<<(int)((size_t)Mdim * Kdim / 16 / 256), 256>>>(inp);
    gemm_k<<<dim3(Ndim / NT, Mdim / MT), 256, SMEM_BYTES>>>(bias, out);
}

// round 12
// speedup vs baseline: 1.2182x; 1.2182x over previous
#include <cuda_runtime.h>
#include <cuda_fp16.h>
#include <cstdint>
#include <cstddef>

#define DI __device__ __forceinline__

static constexpr int Mdim = 8192, Ndim = 4096, Kdim = 4096;
static constexpr int MT = 128, NT = 128, KT = 64;
static constexpr int NKT = Kdim / KT;              // 64
static constexpr int ROWB = 128;                   // 64 fp16 = 128B = one swizzle atom row
static constexpr int TILE_A = 128 * ROWB;          // 16384 B
static constexpr int TILE_B = 128 * ROWB;          // 16384 B
static constexpr int STG = TILE_A + TILE_B;        // 32768 B
static constexpr int NSTG = 3;
static constexpr unsigned SMEM_BYTES = NSTG * STG; // 98304 (x2 CTA = 192KB/SM)

__device__ __half g_wt[(size_t)Ndim * Kdim];       // W^T [n][k], natural layout
__device__ __half g_a [(size_t)Mdim * Kdim];       // A   [m][k], natural layout

DI uint32_t smem_u32(const void* p) {
    uint32_t a;
    asm("{ .reg .u64 t; cvta.to.shared.u64 t, %1; cvt.u32.u64 %0, t; }" : "=r"(a) : "l"(p));
    return a;
}
DI void cpa16(uint32_t dst, const void* src) {
    asm volatile("cp.async.cg.shared.global [%0], [%1], 16;" :: "r"(dst), "l"(src) : "memory");
}
DI void cpa_commit() { asm volatile("cp.async.commit_group;" ::: "memory"); }
template <int N> DI void cpa_wait() {
    asm volatile("cp.async.wait_group %0;" :: "n"(N) : "memory");
}
DI void mma16(float* d, uint32_t a0, uint32_t a1, uint32_t a2, uint32_t a3,
              uint32_t b0, uint32_t b1) {
    asm volatile(
        "mma.sync.aligned.m16n8k16.row.col.f32.f16.f16.f32 "
        "{%0,%1,%2,%3}, {%4,%5,%6,%7}, {%8,%9}, {%0,%1,%2,%3};"
        : "+f"(d[0]), "+f"(d[1]), "+f"(d[2]), "+f"(d[3])
        : "r"(a0), "r"(a1), "r"(a2), "r"(a3), "r"(b0), "r"(b1));
}
#define LDSM4(d0, d1, d2, d3, a)                                               \
    asm volatile("ldmatrix.sync.aligned.m8n8.x4.shared.b16 {%0,%1,%2,%3}, [%4];" \
                 : "=r"(d0), "=r"(d1), "=r"(d2), "=r"(d3) : "r"(a))

// ---------- prep 1: g_wt[n][k] = fp16(q[k][n] * s[k][n/32]), transposed ----------
__global__ void dequant_k(const int* __restrict__ q, const float* __restrict__ s) {
    __shared__ float t[32][33];
    int n0 = blockIdx.x * 32, k0 = blockIdx.y * 32;
    int tx = threadIdx.x, ty = threadIdx.y;   // 32 x 8
    int sb = n0 >> 5;
#pragma unroll
    for (int i = 0; i < 4; i++) {
        int k = k0 + ty + i * 8;
        t[ty + i * 8][tx] = (float)q[(size_t)k * Ndim + n0 + tx] * s[(size_t)k * (Ndim / 32) + sb];
    }
    __syncthreads();
#pragma unroll
    for (int i = 0; i < 4; i++)
        g_wt[(size_t)(n0 + ty + i * 8) * Kdim + k0 + tx] = __float2half_rn(t[tx][ty + i * 8]);
}

// ---------- prep 2: A f32 -> fp16, natural layout (8 values / thread) ----------
__global__ void round_a_k(const float4* __restrict__ in) {
    size_t i = (size_t)blockIdx.x * blockDim.x + threadIdx.x;   // M*K/8 threads
    float4 v0 = in[2 * i], v1 = in[2 * i + 1];
    __half2 h0 = __floats2half2_rn(v0.x, v0.y), h1 = __floats2half2_rn(v0.z, v0.w);
    __half2 h2 = __floats2half2_rn(v1.x, v1.y), h3 = __floats2half2_rn(v1.z, v1.w);
    reinterpret_cast<uint4*>(g_a)[i] =
        make_uint4(*reinterpret_cast<uint32_t*>(&h0), *reinterpret_cast<uint32_t*>(&h1),
                   *reinterpret_cast<uint32_t*>(&h2), *reinterpret_cast<uint32_t*>(&h3));
}

// ---------- GEMM: fp16 m16n8k16, 128x128x64, 128 thr, 64x64 warp tile, 2 CTA/SM ----------
// smem layout: row r (128B) holds its 8 16B-chunks permuted by c ^= (r & 7)  (SW128)
DI void load_tile(uint32_t sb, int tid, int m0, int n0, int jt, int s) {
    const __half* Ap = g_a  + (size_t)m0 * Kdim + jt * KT;
    const __half* Bp = g_wt + (size_t)n0 * Kdim + jt * KT;
    uint32_t base = sb + (uint32_t)s * STG;
#pragma unroll
    for (int i = 0; i < 16; i++) {
        int idx = tid + i * 128;                 // 0..2047
        int half = idx >> 10;                    // 0 = A, 1 = B
        int j = idx & 1023;
        int r = j >> 3, c = j & 7;               // row 0..127, 16B chunk 0..7
        const __half* src = (half ? Bp : Ap) + (size_t)r * Kdim + c * 8;
        uint32_t dst = base + (uint32_t)half * TILE_A
                     + (uint32_t)(r * ROWB + ((c ^ (r & 7)) * 16));
        cpa16(dst, src);
    }
    cpa_commit();
}

__global__ void __launch_bounds__(128, 2) gemm_k(const float* __restrict__ bias,
                                                 float* __restrict__ out) {
    extern __shared__ __align__(1024) char smem[];
    uint32_t sb = smem_u32(smem);
    int tid = threadIdx.x, wid = tid >> 5, lane = tid & 31;
    int qr = lane >> 2, qt = lane & 3;
    int wm = wid >> 1, wn = wid & 1;            // 2 x 2 warp grid, 64x64 warp tile
    int n0 = blockIdx.x * NT, m0 = blockIdx.y * MT;

    // ldmatrix addressing (per thread, stage-invariant parts)
    uint32_t swb  = (uint32_t)(lane & 7) << 4;            // XOR bits for this thread's rows
    uint32_t aRow = (uint32_t)(wm * 64 + (lane & 15));    // A: rows lane%16, chunk-hi lane/16
    uint32_t aHi  = (uint32_t)(lane >> 4);                // 0/1 -> k-chunk select
    uint32_t bRow = (uint32_t)(wn * 64 + (((lane >> 4) & 1) << 3) + (lane & 7));
    uint32_t bHi  = (uint32_t)((lane >> 3) & 1);

    float acc[4][8][4];
#pragma unroll
    for (int a = 0; a < 4; a++)
#pragma unroll
        for (int b = 0; b < 8; b++)
#pragma unroll
            for (int c = 0; c < 4; c++) acc[a][b][c] = 0.f;

    load_tile(sb, tid, m0, n0, 0, 0);
    load_tile(sb, tid, m0, n0, 1, 1);

    for (int jt = 0; jt < NKT; ++jt) {
        if (jt + 1 < NKT) cpa_wait<1>(); else cpa_wait<0>();
        __syncthreads();                        // single barrier per iteration
        if (jt + 2 < NKT)
            load_tile(sb, tid, m0, n0, jt + 2, (jt + 2) % 3);

        int s = jt % 3;
        uint32_t stg  = sb + (uint32_t)s * STG;
        uint32_t aBase = stg + aRow * ROWB;
        uint32_t bBase = stg + TILE_A + bRow * ROWB;

#pragma unroll
        for (int ks = 0; ks < 4; ++ks) {
            uint32_t aOff = (((uint32_t)(ks * 2) + aHi) << 4) ^ swb;
            uint32_t bOff = (((uint32_t)(ks * 2) + bHi) << 4) ^ swb;
            uint32_t af[4][4], bf[8][2];
#pragma unroll
            for (int mi = 0; mi < 4; ++mi)
                LDSM4(af[mi][0], af[mi][1], af[mi][2], af[mi][3],
                      aBase + (uint32_t)(mi * 16 * ROWB) + aOff);
#pragma unroll
            for (int nb = 0; nb < 4; ++nb)
                LDSM4(bf[2 * nb][0], bf[2 * nb][1], bf[2 * nb + 1][0], bf[2 * nb + 1][1],
                      bBase + (uint32_t)(nb * 16 * ROWB) + bOff);
#pragma unroll
            for (int mi = 0; mi < 4; ++mi)
#pragma unroll
                for (int ni = 0; ni < 8; ++ni)
                    mma16(acc[mi][ni], af[mi][0], af[mi][1], af[mi][2], af[mi][3],
                          bf[ni][0], bf[ni][1]);
        }
    }

#pragma unroll
    for (int mi = 0; mi < 4; ++mi) {
        int r0 = m0 + wm * 64 + mi * 16 + qr;
#pragma unroll
        for (int ni = 0; ni < 8; ++ni) {
            int n = n0 + wn * 64 + ni * 8 + 2 * qt;
            float b0 = bias[n], b1 = bias[n + 1];
            float2 v0 = {acc[mi][ni][0] + b0, acc[mi][ni][1] + b1};
            float2 v1 = {acc[mi][ni][2] + b0, acc[mi][ni][3] + b1};
            *reinterpret_cast<float2*>(out + (size_t)r0 * Ndim + n) = v0;
            *reinterpret_cast<float2*>(out + (size_t)(r0 + 8) * Ndim + n) = v1;
        }
    }
}

extern "C" void kernel_launch(void* const* d_in, const int* in_sizes, int n_in,
                              void* d_out, int out_size) {
    const float* inp  = (const float*)d_in[0];
    const int*   qw   = (const int*)d_in[1];
    const float* sc   = (const float*)d_in[2];
    const float* bias = (const float*)d_in[3];
    float* out = (float*)d_out;

    cudaFuncSetAttribute(gemm_k, cudaFuncAttributeMaxDynamicSharedMemorySize, SMEM_BYTES);

    dequant_k<<<dim3(Ndim / 32, Kdim / 32), dim3(32, 8)>>>(qw, sc);
    round_a_k<<<(int)((size_t)Mdim * Kdim / 8 / 256), 256>>>((const float4*)inp);
    gemm_k<<<dim3(Ndim / NT, Mdim / MT), 128, SMEM_BYTES>>>(bias, out);
}

// round 14
// speedup vs baseline: 1.2222x; 1.0032x over previous
#include <cuda_runtime.h>
#include <cuda_fp16.h>
#include <cstdint>
#include <cstddef>

#define DI __device__ __forceinline__

static constexpr int Mdim = 8192, Ndim = 4096, Kdim = 4096;
static constexpr int MT = 128, NT = 128, KT = 64;
static constexpr int NKT = Kdim / KT;              // 64
static constexpr int ROWB = 128;                   // 64 fp16 = 128B = one swizzle atom row
static constexpr int TILE_A = 128 * ROWB;          // 16384 B
static constexpr int TILE_B = 128 * ROWB;          // 16384 B
static constexpr int STG = TILE_A + TILE_B;        // 32768 B
static constexpr int NSTG = 3;
static constexpr unsigned SMEM_BYTES = NSTG * STG; // 98304 (x2 CTA = 192KB/SM)

__device__ __half g_wt[(size_t)Ndim * Kdim];       // W^T [n][k], natural layout
__device__ __half g_a [(size_t)Mdim * Kdim];       // A   [m][k], natural layout

DI uint32_t smem_u32(const void* p) {
    uint32_t a;
    asm("{ .reg .u64 t; cvta.to.shared.u64 t, %1; cvt.u32.u64 %0, t; }" : "=r"(a) : "l"(p));
    return a;
}
DI void cpa16(uint32_t dst, const void* src) {
    asm volatile("cp.async.cg.shared.global [%0], [%1], 16;" :: "r"(dst), "l"(src) : "memory");
}
DI void cpa_commit() { asm volatile("cp.async.commit_group;" ::: "memory"); }
template <int N> DI void cpa_wait() {
    asm volatile("cp.async.wait_group %0;" :: "n"(N) : "memory");
}
DI void mma16(float* d, uint32_t a0, uint32_t a1, uint32_t a2, uint32_t a3,
              uint32_t b0, uint32_t b1) {
    asm volatile(
        "mma.sync.aligned.m16n8k16.row.col.f32.f16.f16.f32 "
        "{%0,%1,%2,%3}, {%4,%5,%6,%7}, {%8,%9}, {%0,%1,%2,%3};"
        : "+f"(d[0]), "+f"(d[1]), "+f"(d[2]), "+f"(d[3])
        : "r"(a0), "r"(a1), "r"(a2), "r"(a3), "r"(b0), "r"(b1));
}
#define LDSM4(d0, d1, d2, d3, a)                                               \
    asm volatile("ldmatrix.sync.aligned.m8n8.x4.shared.b16 {%0,%1,%2,%3}, [%4];" \
                 : "=r"(d0), "=r"(d1), "=r"(d2), "=r"(d3) : "r"(a))

// ---------- prep 1: g_wt[n][k] = fp16(q[k][n] * s[k][n/32]), transposed ----------
// 64k x 32n tile per block, 256 threads; loads and stores both 128B-coalesced.
__global__ void dequant_k(const int* __restrict__ q, const float* __restrict__ s) {
    __shared__ float t[64][35];
    int n0 = blockIdx.x * 32, k0 = blockIdx.y * 64;
    int tid = threadIdx.x;
    int tx = tid & 31, ty = tid >> 5;              // 32 x 8
    int sb = n0 >> 5;
#pragma unroll
    for (int i = 0; i < 8; i++) {
        int kl = ty + i * 8;                       // 0..63
        int k = k0 + kl;
        t[kl][tx] = (float)q[(size_t)k * Ndim + n0 + tx] * s[(size_t)k * (Ndim / 32) + sb];
    }
    __syncthreads();
    // store: warp ty writes rows n_local = ty, ty+8, ty+16, ty+24; lane -> k pair
#pragma unroll
    for (int i = 0; i < 4; i++) {
        int nl = ty + i * 8;
        __half2 h = __floats2half2_rn(t[2 * tx][nl], t[2 * tx + 1][nl]);
        reinterpret_cast<uint32_t*>(g_wt + (size_t)(n0 + nl) * Kdim + k0)[tx] =
            *reinterpret_cast<uint32_t*>(&h);
    }
}

// ---------- prep 2: A f32 -> fp16, natural layout (8 values / thread) ----------
__global__ void round_a_k(const float4* __restrict__ in) {
    size_t i = (size_t)blockIdx.x * blockDim.x + threadIdx.x;   // M*K/8 threads
    float4 v0 = in[2 * i], v1 = in[2 * i + 1];
    __half2 h0 = __floats2half2_rn(v0.x, v0.y), h1 = __floats2half2_rn(v0.z, v0.w);
    __half2 h2 = __floats2half2_rn(v1.x, v1.y), h3 = __floats2half2_rn(v1.z, v1.w);
    reinterpret_cast<uint4*>(g_a)[i] =
        make_uint4(*reinterpret_cast<uint32_t*>(&h0), *reinterpret_cast<uint32_t*>(&h1),
                   *reinterpret_cast<uint32_t*>(&h2), *reinterpret_cast<uint32_t*>(&h3));
}

// ---------- GEMM: fp16 m16n8k16, 128x128x64, 128 thr, 64x64 warp tile, 2 CTA/SM ----------
// smem layout: row r (128B) holds its 8 16B-chunks permuted by c ^= (r & 7)  (SW128)
DI void load_tile(uint32_t sb, int tid, int m0, int n0, int jt, int s) {
    const __half* Ap = g_a  + (size_t)m0 * Kdim + jt * KT;
    const __half* Bp = g_wt + (size_t)n0 * Kdim + jt * KT;
    uint32_t base = sb + (uint32_t)s * STG;
#pragma unroll
    for (int i = 0; i < 16; i++) {
        int idx = tid + i * 128;                 // 0..2047
        int half = idx >> 10;                    // 0 = A, 1 = B
        int j = idx & 1023;
        int r = j >> 3, c = j & 7;               // row 0..127, 16B chunk 0..7
        const __half* src = (half ? Bp : Ap) + (size_t)r * Kdim + c * 8;
        uint32_t dst = base + (uint32_t)half * TILE_A
                     + (uint32_t)(r * ROWB + ((c ^ (r & 7)) * 16));
        cpa16(dst, src);
    }
    cpa_commit();
}

__global__ void __launch_bounds__(128, 2) gemm_k(const float* __restrict__ bias,
                                                 float* __restrict__ out) {
    extern __shared__ __align__(1024) char smem[];
    uint32_t sb = smem_u32(smem);
    int tid = threadIdx.x, wid = tid >> 5, lane = tid & 31;
    int qr = lane >> 2, qt = lane & 3;
    int wm = wid >> 1, wn = wid & 1;            // 2 x 2 warp grid, 64x64 warp tile
    int n0 = blockIdx.x * NT, m0 = blockIdx.y * MT;

    // ldmatrix addressing (per thread, stage-invariant parts)
    uint32_t swb  = (uint32_t)(lane & 7) << 4;            // XOR bits for this thread's rows
    uint32_t aRow = (uint32_t)(wm * 64 + (lane & 15));
    uint32_t aHi  = (uint32_t)(lane >> 4);
    uint32_t bRow = (uint32_t)(wn * 64 + (((lane >> 4) & 1) << 3) + (lane & 7));
    uint32_t bHi  = (uint32_t)((lane >> 3) & 1);

    float acc[4][8][4];
#pragma unroll
    for (int a = 0; a < 4; a++)
#pragma unroll
        for (int b = 0; b < 8; b++)
#pragma unroll
            for (int c = 0; c < 4; c++) acc[a][b][c] = 0.f;

    load_tile(sb, tid, m0, n0, 0, 0);
    load_tile(sb, tid, m0, n0, 1, 1);

    for (int jt = 0; jt < NKT; ++jt) {
        if (jt + 1 < NKT) cpa_wait<1>(); else cpa_wait<0>();
        __syncthreads();                        // makes all warps' tile jt visible
        if (jt + 2 < NKT)
            load_tile(sb, tid, m0, n0, jt + 2, (jt + 2) % 3);

        int s = jt % 3;
        uint32_t stg   = sb + (uint32_t)s * STG;
        uint32_t aBase = stg + aRow * ROWB;
        uint32_t bBase = stg + TILE_A + bRow * ROWB;

#pragma unroll
        for (int ks = 0; ks < 4; ++ks) {
            uint32_t aOff = (((uint32_t)(ks * 2) + aHi) << 4) ^ swb;
            uint32_t bOff = (((uint32_t)(ks * 2) + bHi) << 4) ^ swb;
            uint32_t af[4][4], bf[8][2];
#pragma unroll
            for (int mi = 0; mi < 4; ++mi)
                LDSM4(af[mi][0], af[mi][1], af[mi][2], af[mi][3],
                      aBase + (uint32_t)(mi * 16 * ROWB) + aOff);
#pragma unroll
            for (int nb = 0; nb < 4; ++nb)
                LDSM4(bf[2 * nb][0], bf[2 * nb][1], bf[2 * nb + 1][0], bf[2 * nb + 1][1],
                      bBase + (uint32_t)(nb * 16 * ROWB) + bOff);
#pragma unroll
            for (int mi = 0; mi < 4; ++mi)
#pragma unroll
                for (int ni = 0; ni < 8; ++ni)
                    mma16(acc[mi][ni], af[mi][0], af[mi][1], af[mi][2], af[mi][3],
                          bf[ni][0], bf[ni][1]);
        }
    }

#pragma unroll
    for (int mi = 0; mi < 4; ++mi) {
        int r0 = m0 + wm * 64 + mi * 16 + qr;
        float* o0 = out + (size_t)r0 * Ndim;
        float* o1 = out + (size_t)(r0 + 8) * Ndim;
#pragma unroll
        for (int ni = 0; ni < 8; ++ni) {
            int n = n0 + wn * 64 + ni * 8 + 2 * qt;
            float b0 = __ldg(bias + n), b1 = __ldg(bias + n + 1);
            float2 v0 = {acc[mi][ni][0] + b0, acc[mi][ni][1] + b1};
            float2 v1 = {acc[mi][ni][2] + b0, acc[mi][ni][3] + b1};
            *reinterpret_cast<float2*>(o0 + n) = v0;
            *reinterpret_cast<float2*>(o1 + n) = v1;
        }
    }
}

extern "C" void kernel_launch(void* const* d_in, const int* in_sizes, int n_in,
                              void* d_out, int out_size) {
    const float* inp  = (const float*)d_in[0];
    const int*   qw   = (const int*)d_in[1];
    const float* sc   = (const float*)d_in[2];
    const float* bias = (const float*)d_in[3];
    float* out = (float*)d_out;

    cudaFuncSetAttribute(gemm_k, cudaFuncAttributeMaxDynamicSharedMemorySize, SMEM_BYTES);

    dequant_k<<<dim3(Ndim / 32, Kdim / 64), 256>>>(qw, sc);
    round_a_k<<<(int)((size_t)Mdim * Kdim / 8 / 256), 256>>>((const float4*)inp);
    gemm_k<<<dim3(Ndim / NT, Mdim / MT), 128, SMEM_BYTES>>>(bias, out);
}

// round 15
// speedup vs baseline: 1.2664x; 1.0362x over previous
#include <cuda_runtime.h>
#include <cuda_fp16.h>
#include <cstdint>
#include <cstddef>

#define DI __device__ __forceinline__

static constexpr int Mdim = 8192, Ndim = 4096, Kdim = 4096;
static constexpr int MT = 128, NT = 128, KT = 64;
static constexpr int NKT = Kdim / KT;              // 64
static constexpr int ROWB = 128;                   // 64 fp16 = 128B = one swizzle atom row
static constexpr int TILE_A = 128 * ROWB;          // 16384 B
static constexpr int TILE_B = 128 * ROWB;          // 16384 B
static constexpr int STG = TILE_A + TILE_B;        // 32768 B
static constexpr int NSTG = 3;
static constexpr unsigned SMEM_BYTES = NSTG * STG; // 98304 (x2 CTA = 192KB/SM)

__device__ __half g_wt[(size_t)Ndim * Kdim];       // W^T [n][k], natural layout
__device__ __half g_a [(size_t)Mdim * Kdim];       // A   [m][k], natural layout

DI uint32_t smem_u32(const void* p) {
    uint32_t a;
    asm("{ .reg .u64 t; cvta.to.shared.u64 t, %1; cvt.u32.u64 %0, t; }" : "=r"(a) : "l"(p));
    return a;
}
DI void cpa16(uint32_t dst, const void* src) {
    asm volatile("cp.async.cg.shared.global [%0], [%1], 16;" :: "r"(dst), "l"(src) : "memory");
}
DI void cpa_commit() { asm volatile("cp.async.commit_group;" ::: "memory"); }
template <int N> DI void cpa_wait() {
    asm volatile("cp.async.wait_group %0;" :: "n"(N) : "memory");
}
DI void mma16(float* d, uint32_t a0, uint32_t a1, uint32_t a2, uint32_t a3,
              uint32_t b0, uint32_t b1) {
    asm volatile(
        "mma.sync.aligned.m16n8k16.row.col.f32.f16.f16.f32 "
        "{%0,%1,%2,%3}, {%4,%5,%6,%7}, {%8,%9}, {%0,%1,%2,%3};"
        : "+f"(d[0]), "+f"(d[1]), "+f"(d[2]), "+f"(d[3])
        : "r"(a0), "r"(a1), "r"(a2), "r"(a3), "r"(b0), "r"(b1));
}
#define LDSM4(d0, d1, d2, d3, a)                                               \
    asm volatile("ldmatrix.sync.aligned.m8n8.x4.shared.b16 {%0,%1,%2,%3}, [%4];" \
                 : "=r"(d0), "=r"(d1), "=r"(d2), "=r"(d3) : "r"(a))

// ---------- prep 1: g_wt[n][k] = fp16(q[k][n] * s[k][n/32]), transposed ----------
__global__ void dequant_k(const int* __restrict__ q, const float* __restrict__ s) {
    __shared__ float t[64][35];
    int n0 = blockIdx.x * 32, k0 = blockIdx.y * 64;
    int tid = threadIdx.x;
    int tx = tid & 31, ty = tid >> 5;              // 32 x 8
    int sb = n0 >> 5;
#pragma unroll
    for (int i = 0; i < 8; i++) {
        int kl = ty + i * 8;
        int k = k0 + kl;
        t[kl][tx] = (float)q[(size_t)k * Ndim + n0 + tx] * s[(size_t)k * (Ndim / 32) + sb];
    }
    __syncthreads();
#pragma unroll
    for (int i = 0; i < 4; i++) {
        int nl = ty + i * 8;
        __half2 h = __floats2half2_rn(t[2 * tx][nl], t[2 * tx + 1][nl]);
        reinterpret_cast<uint32_t*>(g_wt + (size_t)(n0 + nl) * Kdim + k0)[tx] =
            *reinterpret_cast<uint32_t*>(&h);
    }
}

// ---------- prep 2: A f32 -> fp16, natural layout (8 values / thread) ----------
__global__ void round_a_k(const float4* __restrict__ in) {
    size_t i = (size_t)blockIdx.x * blockDim.x + threadIdx.x;   // M*K/8 threads
    float4 v0 = in[2 * i], v1 = in[2 * i + 1];
    __half2 h0 = __floats2half2_rn(v0.x, v0.y), h1 = __floats2half2_rn(v0.z, v0.w);
    __half2 h2 = __floats2half2_rn(v1.x, v1.y), h3 = __floats2half2_rn(v1.z, v1.w);
    reinterpret_cast<uint4*>(g_a)[i] =
        make_uint4(*reinterpret_cast<uint32_t*>(&h0), *reinterpret_cast<uint32_t*>(&h1),
                   *reinterpret_cast<uint32_t*>(&h2), *reinterpret_cast<uint32_t*>(&h3));
}

// ---------- GEMM: fp16 m16n8k16, 128x128x64, 128 thr, 64x64 warp tile, 2 CTA/SM ----------
DI void load_tile(uint32_t sb, int tid, int m0, int n0, int jt, int s) {
    const __half* Ap = g_a  + (size_t)m0 * Kdim + jt * KT;
    const __half* Bp = g_wt + (size_t)n0 * Kdim + jt * KT;
    uint32_t base = sb + (uint32_t)s * STG;
#pragma unroll
    for (int i = 0; i < 16; i++) {
        int idx = tid + i * 128;                 // 0..2047
        int half = idx >> 10;                    // 0 = A, 1 = B
        int j = idx & 1023;
        int r = j >> 3, c = j & 7;               // row 0..127, 16B chunk 0..7
        const __half* src = (half ? Bp : Ap) + (size_t)r * Kdim + c * 8;
        uint32_t dst = base + (uint32_t)half * TILE_A
                     + (uint32_t)(r * ROWB + ((c ^ (r & 7)) * 16));
        cpa16(dst, src);
    }
    cpa_commit();
}

__global__ void __launch_bounds__(128, 2) gemm_k(const float* __restrict__ bias,
                                                 float* __restrict__ out) {
    extern __shared__ __align__(1024) char smem[];
    uint32_t sb = smem_u32(smem);
    int tid = threadIdx.x, wid = tid >> 5, lane = tid & 31;
    int qr = lane >> 2, qt = lane & 3;
    int wm = wid >> 1, wn = wid & 1;            // 2 x 2 warp grid, 64x64 warp tile
    int n0 = blockIdx.x * NT, m0 = blockIdx.y * MT;

    uint32_t swb  = (uint32_t)(lane & 7) << 4;
    uint32_t aRow = (uint32_t)(wm * 64 + (lane & 15));
    uint32_t aHi  = (uint32_t)(lane >> 4);
    uint32_t bRow = (uint32_t)(wn * 64 + (((lane >> 4) & 1) << 3) + (lane & 7));
    uint32_t bHi  = (uint32_t)((lane >> 3) & 1);

    float acc[4][8][4];
#pragma unroll
    for (int a = 0; a < 4; a++)
#pragma unroll
        for (int b = 0; b < 8; b++)
#pragma unroll
            for (int c = 0; c < 4; c++) acc[a][b][c] = 0.f;

    load_tile(sb, tid, m0, n0, 0, 0);
    load_tile(sb, tid, m0, n0, 1, 1);

    for (int jt = 0; jt < NKT; ++jt) {
        if (jt + 1 < NKT) cpa_wait<1>(); else cpa_wait<0>();
        __syncthreads();                        // makes all warps' tile jt visible

        int s = jt % 3;
        uint32_t stg   = sb + (uint32_t)s * STG;
        uint32_t aBase = stg + aRow * ROWB;
        uint32_t bBase = stg + TILE_A + bRow * ROWB;

#pragma unroll
        for (int ks = 0; ks < 4; ++ks) {
            uint32_t aOff = (((uint32_t)(ks * 2) + aHi) << 4) ^ swb;
            uint32_t bOff = (((uint32_t)(ks * 2) + bHi) << 4) ^ swb;
            uint32_t af[4][4], bf[8][2];
#pragma unroll
            for (int mi = 0; mi < 4; ++mi)
                LDSM4(af[mi][0], af[mi][1], af[mi][2], af[mi][3],
                      aBase + (uint32_t)(mi * 16 * ROWB) + aOff);
#pragma unroll
            for (int nb = 0; nb < 4; ++nb)
                LDSM4(bf[2 * nb][0], bf[2 * nb][1], bf[2 * nb + 1][0], bf[2 * nb + 1][1],
                      bBase + (uint32_t)(nb * 16 * ROWB) + bOff);
            // issue next tile's copies AFTER the first LDSM batch so the LDGSTS
            // burst hides under the ks=0 MMA block instead of delaying it
            if (ks == 1 && jt + 2 < NKT)
                load_tile(sb, tid, m0, n0, jt + 2, (jt + 2) % 3);
#pragma unroll
            for (int mi = 0; mi < 4; ++mi)
#pragma unroll
                for (int ni = 0; ni < 8; ++ni)
                    mma16(acc[mi][ni], af[mi][0], af[mi][1], af[mi][2], af[mi][3],
                          bf[ni][0], bf[ni][1]);
        }
    }

#pragma unroll
    for (int mi = 0; mi < 4; ++mi) {
        int r0 = m0 + wm * 64 + mi * 16 + qr;
        float* o0 = out + (size_t)r0 * Ndim;
        float* o1 = out + (size_t)(r0 + 8) * Ndim;
#pragma unroll
        for (int ni = 0; ni < 8; ++ni) {
            int n = n0 + wn * 64 + ni * 8 + 2 * qt;
            float b0 = __ldg(bias + n), b1 = __ldg(bias + n + 1);
            float2 v0 = {acc[mi][ni][0] + b0, acc[mi][ni][1] + b1};
            float2 v1 = {acc[mi][ni][2] + b0, acc[mi][ni][3] + b1};
            *reinterpret_cast<float2*>(o0 + n) = v0;
            *reinterpret_cast<float2*>(o1 + n) = v1;
        }
    }
}

extern "C" void kernel_launch(void* const* d_in, const int* in_sizes, int n_in,
                              void* d_out, int out_size) {
    const float* inp  = (const float*)d_in[0];
    const int*   qw   = (const int*)d_in[1];
    const float* sc   = (const float*)d_in[2];
    const float* bias = (const float*)d_in[3];
    float* out = (float*)d_out;

    // one-time creation of side stream + events (not device-memory allocations;
    // identical launch pattern every call, so the captured graph is deterministic)
    static cudaStream_t s2 = nullptr;
    static cudaEvent_t eFork = nullptr, eJoin = nullptr;
    if (!s2) {
        cudaStreamCreateWithFlags(&s2, cudaStreamNonBlocking);
        cudaEventCreateWithFlags(&eFork, cudaEventDisableTiming);
        cudaEventCreateWithFlags(&eJoin, cudaEventDisableTiming);
    }

    cudaFuncSetAttribute(gemm_k, cudaFuncAttributeMaxDynamicSharedMemorySize, SMEM_BYTES);

    // fork: round_a on side stream, dequant on main stream, join before gemm
    cudaEventRecord(eFork, 0);
    cudaStreamWaitEvent(s2, eFork, 0);
    round_a_k<<<(int)((size_t)Mdim * Kdim / 8 / 256), 256, 0, s2>>>((const float4*)inp);
    cudaEventRecord(eJoin, s2);

    dequant_k<<<dim3(Ndim / 32, Kdim / 64), 256>>>(qw, sc);

    cudaStreamWaitEvent(0, eJoin, 0);
    gemm_k<<<dim3(Ndim / NT, Mdim / MT), 128, SMEM_BYTES>>>(bias, out);
}

// round 16
// speedup vs baseline: 1.3036x; 1.0294x over previous
#include <cuda_runtime.h>
#include <cuda_fp16.h>
#include <cstdint>
#include <cstddef>

#define DI __device__ __forceinline__

static constexpr int Mdim = 8192, Ndim = 4096, Kdim = 4096;
static constexpr int MT = 128, NT = 128, KT = 64;
static constexpr int NKT = Kdim / KT;              // 64
static constexpr int ROWB = 128;                   // 64 fp16 = 128B = one swizzle atom row
static constexpr int TILE_A = 128 * ROWB;          // 16384 B
static constexpr int TILE_B = 128 * ROWB;          // 16384 B
static constexpr int STG = TILE_A + TILE_B;        // 32768 B
static constexpr int NSTG = 3;
static constexpr int EPI_STRIDE = 132;             // floats; (4*row)%32 distinct banks
static constexpr unsigned SMEM_BYTES = NSTG * STG; // 98304 >= 128*132*4=67584 for epilogue

__device__ __half g_wt[(size_t)Ndim * Kdim];       // W^T [n][k], natural layout
__device__ __half g_a [(size_t)Mdim * Kdim];       // A   [m][k], natural layout

DI uint32_t smem_u32(const void* p) {
    uint32_t a;
    asm("{ .reg .u64 t; cvta.to.shared.u64 t, %1; cvt.u32.u64 %0, t; }" : "=r"(a) : "l"(p));
    return a;
}
DI void cpa16(uint32_t dst, const void* src) {
    asm volatile("cp.async.cg.shared.global [%0], [%1], 16;" :: "r"(dst), "l"(src) : "memory");
}
DI void cpa_commit() { asm volatile("cp.async.commit_group;" ::: "memory"); }
template <int N> DI void cpa_wait() {
    asm volatile("cp.async.wait_group %0;" :: "n"(N) : "memory");
}
DI void mma16(float* d, uint32_t a0, uint32_t a1, uint32_t a2, uint32_t a3,
              uint32_t b0, uint32_t b1) {
    asm volatile(
        "mma.sync.aligned.m16n8k16.row.col.f32.f16.f16.f32 "
        "{%0,%1,%2,%3}, {%4,%5,%6,%7}, {%8,%9}, {%0,%1,%2,%3};"
        : "+f"(d[0]), "+f"(d[1]), "+f"(d[2]), "+f"(d[3])
        : "r"(a0), "r"(a1), "r"(a2), "r"(a3), "r"(b0), "r"(b1));
}
#define LDSM4(d0, d1, d2, d3, a)                                               \
    asm volatile("ldmatrix.sync.aligned.m8n8.x4.shared.b16 {%0,%1,%2,%3}, [%4];" \
                 : "=r"(d0), "=r"(d1), "=r"(d2), "=r"(d3) : "r"(a))

// ---------- prep 1: g_wt[n][k] = fp16(q[k][n] * s[k][n/32]), transposed ----------
__global__ void dequant_k(const int* __restrict__ q, const float* __restrict__ s) {
    __shared__ float t[64][35];
    int n0 = blockIdx.x * 32, k0 = blockIdx.y * 64;
    int tid = threadIdx.x;
    int tx = tid & 31, ty = tid >> 5;              // 32 x 8
    int sb = n0 >> 5;
#pragma unroll
    for (int i = 0; i < 8; i++) {
        int kl = ty + i * 8;
        int k = k0 + kl;
        t[kl][tx] = (float)q[(size_t)k * Ndim + n0 + tx] * s[(size_t)k * (Ndim / 32) + sb];
    }
    __syncthreads();
#pragma unroll
    for (int i = 0; i < 4; i++) {
        int nl = ty + i * 8;
        __half2 h = __floats2half2_rn(t[2 * tx][nl], t[2 * tx + 1][nl]);
        reinterpret_cast<uint32_t*>(g_wt + (size_t)(n0 + nl) * Kdim + k0)[tx] =
            *reinterpret_cast<uint32_t*>(&h);
    }
}

// ---------- prep 2: A f32 -> fp16 (8 values / thread) ----------
__global__ void round_a_k(const float4* __restrict__ in) {
    size_t i = (size_t)blockIdx.x * blockDim.x + threadIdx.x;   // M*K/8 threads
    float4 v0 = in[2 * i], v1 = in[2 * i + 1];
    __half2 h0 = __floats2half2_rn(v0.x, v0.y), h1 = __floats2half2_rn(v0.z, v0.w);
    __half2 h2 = __floats2half2_rn(v1.x, v1.y), h3 = __floats2half2_rn(v1.z, v1.w);
    reinterpret_cast<uint4*>(g_a)[i] =
        make_uint4(*reinterpret_cast<uint32_t*>(&h0), *reinterpret_cast<uint32_t*>(&h1),
                   *reinterpret_cast<uint32_t*>(&h2), *reinterpret_cast<uint32_t*>(&h3));
}

// ---------- GEMM: fp16 m16n8k16, 128x128x64, 128 thr, 64x64 warp tile, 2 CTA/SM ----------
// half-tile loads: phase 0 = A (8 chunks/thread-slot), phase 1 = B
DI void load_half(uint32_t sb, int tid, int m0, int n0, int jt, int s, int phase) {
    const __half* P = (phase ? g_wt + (size_t)n0 * Kdim : g_a + (size_t)m0 * Kdim) + jt * KT;
    uint32_t base = sb + (uint32_t)s * STG + (uint32_t)phase * TILE_A;
#pragma unroll
    for (int i = 0; i < 8; i++) {
        int j = tid + i * 128;                   // 0..1023
        int r = j >> 3, c = j & 7;               // row 0..127, 16B chunk 0..7
        cpa16(base + (uint32_t)(r * ROWB + ((c ^ (r & 7)) * 16)),
              P + (size_t)r * Kdim + c * 8);
    }
}

__global__ void __launch_bounds__(128, 2) gemm_k(const float* __restrict__ bias,
                                                 float* __restrict__ out) {
    extern __shared__ __align__(1024) char smem[];
    uint32_t sb = smem_u32(smem);
    int tid = threadIdx.x, wid = tid >> 5, lane = tid & 31;
    int qr = lane >> 2, qt = lane & 3;
    int wm = wid >> 1, wn = wid & 1;            // 2 x 2 warp grid, 64x64 warp tile
    int n0 = blockIdx.x * NT, m0 = blockIdx.y * MT;

    uint32_t swb  = (uint32_t)(lane & 7) << 4;
    uint32_t aRow = (uint32_t)(wm * 64 + (lane & 15));
    uint32_t aHi  = (uint32_t)(lane >> 4);
    uint32_t bRow = (uint32_t)(wn * 64 + (((lane >> 4) & 1) << 3) + (lane & 7));
    uint32_t bHi  = (uint32_t)((lane >> 3) & 1);

    float acc[4][8][4];
#pragma unroll
    for (int a = 0; a < 4; a++)
#pragma unroll
        for (int b = 0; b < 8; b++)
#pragma unroll
            for (int c = 0; c < 4; c++) acc[a][b][c] = 0.f;

    load_half(sb, tid, m0, n0, 0, 0, 0); load_half(sb, tid, m0, n0, 0, 0, 1); cpa_commit();
    load_half(sb, tid, m0, n0, 1, 1, 0); load_half(sb, tid, m0, n0, 1, 1, 1); cpa_commit();

    for (int jt = 0; jt < NKT; ++jt) {
        if (jt + 1 < NKT) cpa_wait<1>(); else cpa_wait<0>();
        __syncthreads();                        // makes all warps' tile jt visible

        int s = jt % 3;
        uint32_t stg   = sb + (uint32_t)s * STG;
        uint32_t aBase = stg + aRow * ROWB;
        uint32_t bBase = stg + TILE_A + bRow * ROWB;

#pragma unroll
        for (int ks = 0; ks < 4; ++ks) {
            uint32_t aOff = (((uint32_t)(ks * 2) + aHi) << 4) ^ swb;
            uint32_t bOff = (((uint32_t)(ks * 2) + bHi) << 4) ^ swb;
            uint32_t af[4][4], bf[8][2];
#pragma unroll
            for (int mi = 0; mi < 4; ++mi)
                LDSM4(af[mi][0], af[mi][1], af[mi][2], af[mi][3],
                      aBase + (uint32_t)(mi * 16 * ROWB) + aOff);
#pragma unroll
            for (int nb = 0; nb < 4; ++nb)
                LDSM4(bf[2 * nb][0], bf[2 * nb][1], bf[2 * nb + 1][0], bf[2 * nb + 1][1],
                      bBase + (uint32_t)(nb * 16 * ROWB) + bOff);
            // split next-tile copy burst: A-half under ks=1 MMAs, B-half under ks=2
            if (jt + 2 < NKT) {
                if (ks == 1) load_half(sb, tid, m0, n0, jt + 2, (jt + 2) % 3, 0);
                if (ks == 2) { load_half(sb, tid, m0, n0, jt + 2, (jt + 2) % 3, 1); cpa_commit(); }
            }
#pragma unroll
            for (int mi = 0; mi < 4; ++mi)
#pragma unroll
                for (int ni = 0; ni < 8; ++ni)
                    mma16(acc[mi][ni], af[mi][0], af[mi][1], af[mi][2], af[mi][3],
                          bf[ni][0], bf[ni][1]);
        }
    }

    // ---- epilogue: stage through smem for fully coalesced float4 stores ----
    __syncthreads();                            // mainloop smem reads done
    float* eb = reinterpret_cast<float*>(smem);
#pragma unroll
    for (int mi = 0; mi < 4; ++mi) {
        int r0 = wm * 64 + mi * 16 + qr;
#pragma unroll
        for (int ni = 0; ni < 8; ++ni) {
            int c = wn * 64 + ni * 8 + 2 * qt;
            *reinterpret_cast<float2*>(eb + r0 * EPI_STRIDE + c) =
                make_float2(acc[mi][ni][0], acc[mi][ni][1]);
            *reinterpret_cast<float2*>(eb + (r0 + 8) * EPI_STRIDE + c) =
                make_float2(acc[mi][ni][2], acc[mi][ni][3]);
        }
    }
    __syncthreads();
    {
        int col = (tid & 31) * 4;               // 0..124
        int rbase = tid >> 5;                   // 0..3
        float4 bv = *reinterpret_cast<const float4*>(bias + n0 + col);
#pragma unroll 8
        for (int p = 0; p < 32; ++p) {
            int r = rbase + p * 4;
            float4 v = *reinterpret_cast<float4*>(eb + r * EPI_STRIDE + col);
            v.x += bv.x; v.y += bv.y; v.z += bv.z; v.w += bv.w;
            *reinterpret_cast<float4*>(out + (size_t)(m0 + r) * Ndim + n0 + col) = v;
        }
    }
}

extern "C" void kernel_launch(void* const* d_in, const int* in_sizes, int n_in,
                              void* d_out, int out_size) {
    const float* inp  = (const float*)d_in[0];
    const int*   qw   = (const int*)d_in[1];
    const float* sc   = (const float*)d_in[2];
    const float* bias = (const float*)d_in[3];
    float* out = (float*)d_out;

    static cudaStream_t s2 = nullptr;
    static cudaEvent_t eFork = nullptr, eJoin = nullptr;
    if (!s2) {
        cudaStreamCreateWithFlags(&s2, cudaStreamNonBlocking);
        cudaEventCreateWithFlags(&eFork, cudaEventDisableTiming);
        cudaEventCreateWithFlags(&eJoin, cudaEventDisableTiming);
    }

    cudaFuncSetAttribute(gemm_k, cudaFuncAttributeMaxDynamicSharedMemorySize, SMEM_BYTES);

    cudaEventRecord(eFork, 0);
    cudaStreamWaitEvent(s2, eFork, 0);
    round_a_k<<<(int)((size_t)Mdim * Kdim / 8 / 256), 256, 0, s2>>>((const float4*)inp);
    cudaEventRecord(eJoin, s2);

    dequant_k<<<dim3(Ndim / 32, Kdim / 64), 256>>>(qw, sc);

    cudaStreamWaitEvent(0, eJoin, 0);
    gemm_k<<<dim3(Ndim / NT, Mdim / MT), 128, SMEM_BYTES>>>(bias, out);
}

// round 17
// speedup vs baseline: 1.3648x; 1.0469x over previous
#include <cuda_runtime.h>
#include <cuda_fp16.h>
#include <cstdint>
#include <cstddef>

#define DI __device__ __forceinline__

static constexpr int Mdim = 8192, Ndim = 4096, Kdim = 4096;
static constexpr int MT = 128, NT = 128, KT = 64;
static constexpr int NKT = Kdim / KT;              // 64
static constexpr int ROWB = 128;                   // 64 fp16 = 128B = one swizzle atom row
static constexpr int TILE_A = 128 * ROWB;          // 16384 B
static constexpr int TILE_B = 128 * ROWB;          // 16384 B
static constexpr int STG = TILE_A + TILE_B;        // 32768 B
static constexpr int NSTG = 3;
static constexpr int EPI_STRIDE = 132;             // floats; conflict-free epilogue banks
static constexpr unsigned SMEM_BYTES = NSTG * STG; // 98304 (x2 CTA = 192KB/SM)

__device__ __half g_wt[(size_t)Ndim * Kdim];       // W^T [n][k], natural layout
__device__ __half g_a [(size_t)Mdim * Kdim];       // A   [m][k], natural layout

DI uint32_t smem_u32(const void* p) {
    uint32_t a;
    asm("{ .reg .u64 t; cvta.to.shared.u64 t, %1; cvt.u32.u64 %0, t; }" : "=r"(a) : "l"(p));
    return a;
}
DI void cpa16(uint32_t dst, const void* src) {
    asm volatile("cp.async.cg.shared.global [%0], [%1], 16;" :: "r"(dst), "l"(src) : "memory");
}
DI void cpa_commit() { asm volatile("cp.async.commit_group;" ::: "memory"); }
template <int N> DI void cpa_wait() {
    asm volatile("cp.async.wait_group %0;" :: "n"(N) : "memory");
}
DI void mma16(float* d, uint32_t a0, uint32_t a1, uint32_t a2, uint32_t a3,
              uint32_t b0, uint32_t b1) {
    asm volatile(
        "mma.sync.aligned.m16n8k16.row.col.f32.f16.f16.f32 "
        "{%0,%1,%2,%3}, {%4,%5,%6,%7}, {%8,%9}, {%0,%1,%2,%3};"
        : "+f"(d[0]), "+f"(d[1]), "+f"(d[2]), "+f"(d[3])
        : "r"(a0), "r"(a1), "r"(a2), "r"(a3), "r"(b0), "r"(b1));
}
#define LDSM4(d0, d1, d2, d3, a)                                               \
    asm volatile("ldmatrix.sync.aligned.m8n8.x4.shared.b16 {%0,%1,%2,%3}, [%4];" \
                 : "=r"(d0), "=r"(d1), "=r"(d2), "=r"(d3) : "r"(a))

// ---------- prep 1: g_wt[n][k] = fp16(q[k][n] * s[k][n/32]), transposed ----------
__global__ void dequant_k(const int* __restrict__ q, const float* __restrict__ s) {
    __shared__ float t[64][35];
    int n0 = blockIdx.x * 32, k0 = blockIdx.y * 64;
    int tid = threadIdx.x;
    int tx = tid & 31, ty = tid >> 5;              // 32 x 8
    int sb = n0 >> 5;
#pragma unroll
    for (int i = 0; i < 8; i++) {
        int kl = ty + i * 8;
        int k = k0 + kl;
        t[kl][tx] = (float)q[(size_t)k * Ndim + n0 + tx] * s[(size_t)k * (Ndim / 32) + sb];
    }
    __syncthreads();
#pragma unroll
    for (int i = 0; i < 4; i++) {
        int nl = ty + i * 8;
        __half2 h = __floats2half2_rn(t[2 * tx][nl], t[2 * tx + 1][nl]);
        reinterpret_cast<uint32_t*>(g_wt + (size_t)(n0 + nl) * Kdim + k0)[tx] =
            *reinterpret_cast<uint32_t*>(&h);
    }
}

// ---------- prep 2: A f32 -> fp16 (8 values / thread) ----------
__global__ void round_a_k(const float4* __restrict__ in) {
    size_t i = (size_t)blockIdx.x * blockDim.x + threadIdx.x;   // M*K/8 threads
    float4 v0 = in[2 * i], v1 = in[2 * i + 1];
    __half2 h0 = __floats2half2_rn(v0.x, v0.y), h1 = __floats2half2_rn(v0.z, v0.w);
    __half2 h2 = __floats2half2_rn(v1.x, v1.y), h3 = __floats2half2_rn(v1.z, v1.w);
    reinterpret_cast<uint4*>(g_a)[i] =
        make_uint4(*reinterpret_cast<uint32_t*>(&h0), *reinterpret_cast<uint32_t*>(&h1),
                   *reinterpret_cast<uint32_t*>(&h2), *reinterpret_cast<uint32_t*>(&h3));
}

// ---------- GEMM: fp16 m16n8k16, 128x128x64, 128 thr, 64x64 warp tile, 2 CTA/SM ----------
// quarter-tile loads: qtr 0/1 = A halves, 2/3 = B halves (4 cp.async each)
DI void load_quarter(uint32_t sb, int tid, int m0, int n0, int jt, int s, int qtr) {
    int phase = qtr >> 1;                        // 0 = A, 1 = B
    const __half* P = (phase ? g_wt + (size_t)n0 * Kdim : g_a + (size_t)m0 * Kdim) + jt * KT;
    uint32_t base = sb + (uint32_t)s * STG + (uint32_t)phase * TILE_A;
    int i0 = (qtr & 1) * 4;
#pragma unroll
    for (int i = 0; i < 4; i++) {
        int j = tid + (i0 + i) * 128;            // 0..1023
        int r = j >> 3, c = j & 7;               // row 0..127, 16B chunk 0..7
        cpa16(base + (uint32_t)(r * ROWB + ((c ^ (r & 7)) * 16)),
              P + (size_t)r * Kdim + c * 8);
    }
}
DI void load_tile_full(uint32_t sb, int tid, int m0, int n0, int jt, int s) {
#pragma unroll
    for (int q = 0; q < 4; q++) load_quarter(sb, tid, m0, n0, jt, s, q);
    cpa_commit();
}

__global__ void __launch_bounds__(128, 2) gemm_k(const float* __restrict__ bias,
                                                 float* __restrict__ out) {
    extern __shared__ __align__(1024) char smem[];
    uint32_t sb = smem_u32(smem);
    int tid = threadIdx.x, wid = tid >> 5, lane = tid & 31;
    int qr = lane >> 2, qt = lane & 3;
    int wm = wid >> 1, wn = wid & 1;            // 2 x 2 warp grid, 64x64 warp tile
    int n0 = blockIdx.x * NT, m0 = blockIdx.y * MT;

    uint32_t swb  = (uint32_t)(lane & 7) << 4;
    uint32_t aRow = (uint32_t)(wm * 64 + (lane & 15));
    uint32_t aHi  = (uint32_t)(lane >> 4);
    uint32_t bRow = (uint32_t)(wn * 64 + (((lane >> 4) & 1) << 3) + (lane & 7));
    uint32_t bHi  = (uint32_t)((lane >> 3) & 1);

    float acc[4][8][4];
#pragma unroll
    for (int a = 0; a < 4; a++)
#pragma unroll
        for (int b = 0; b < 8; b++)
#pragma unroll
            for (int c = 0; c < 4; c++) acc[a][b][c] = 0.f;

    load_tile_full(sb, tid, m0, n0, 0, 0);
    load_tile_full(sb, tid, m0, n0, 1, 1);

#pragma unroll 3
    for (int jt = 0; jt < NKT; ++jt) {
        if (jt + 1 < NKT) cpa_wait<1>(); else cpa_wait<0>();
        __syncthreads();                        // makes all warps' tile jt visible

        int s = jt % 3;
        uint32_t stg   = sb + (uint32_t)s * STG;
        uint32_t aBase = stg + aRow * ROWB;
        uint32_t bBase = stg + TILE_A + bRow * ROWB;

#pragma unroll
        for (int ks = 0; ks < 4; ++ks) {
            uint32_t aOff = (((uint32_t)(ks * 2) + aHi) << 4) ^ swb;
            uint32_t bOff = (((uint32_t)(ks * 2) + bHi) << 4) ^ swb;
            uint32_t af[4][4], bf[8][2];
#pragma unroll
            for (int mi = 0; mi < 4; ++mi)
                LDSM4(af[mi][0], af[mi][1], af[mi][2], af[mi][3],
                      aBase + (uint32_t)(mi * 16 * ROWB) + aOff);
#pragma unroll
            for (int nb = 0; nb < 4; ++nb)
                LDSM4(bf[2 * nb][0], bf[2 * nb][1], bf[2 * nb + 1][0], bf[2 * nb + 1][1],
                      bBase + (uint32_t)(nb * 16 * ROWB) + bOff);
            // quarter of next tile's copies under each ks block; commit at ks=3
            if (jt + 2 < NKT) {
                load_quarter(sb, tid, m0, n0, jt + 2, (jt + 2) % 3, ks);
                if (ks == 3) cpa_commit();
            }
#pragma unroll
            for (int mi = 0; mi < 4; ++mi)
#pragma unroll
                for (int ni = 0; ni < 8; ++ni)
                    mma16(acc[mi][ni], af[mi][0], af[mi][1], af[mi][2], af[mi][3],
                          bf[ni][0], bf[ni][1]);
        }
    }

    // ---- epilogue: stage through smem for fully coalesced float4 stores ----
    __syncthreads();                            // mainloop smem reads done
    float* eb = reinterpret_cast<float*>(smem);
#pragma unroll
    for (int mi = 0; mi < 4; ++mi) {
        int r0 = wm * 64 + mi * 16 + qr;
#pragma unroll
        for (int ni = 0; ni < 8; ++ni) {
            int c = wn * 64 + ni * 8 + 2 * qt;
            *reinterpret_cast<float2*>(eb + r0 * EPI_STRIDE + c) =
                make_float2(acc[mi][ni][0], acc[mi][ni][1]);
            *reinterpret_cast<float2*>(eb + (r0 + 8) * EPI_STRIDE + c) =
                make_float2(acc[mi][ni][2], acc[mi][ni][3]);
        }
    }
    __syncthreads();
    {
        int col = (tid & 31) * 4;               // 0..124
        int rbase = tid >> 5;                   // 0..3
        float4 bv = *reinterpret_cast<const float4*>(bias + n0 + col);
#pragma unroll 8
        for (int p = 0; p < 32; ++p) {
            int r = rbase + p * 4;
            float4 v = *reinterpret_cast<float4*>(eb + r * EPI_STRIDE + col);
            v.x += bv.x; v.y += bv.y; v.z += bv.z; v.w += bv.w;
            *reinterpret_cast<float4*>(out + (size_t)(m0 + r) * Ndim + n0 + col) = v;
        }
    }
}

extern "C" void kernel_launch(void* const* d_in, const int* in_sizes, int n_in,
                              void* d_out, int out_size) {
    const float* inp  = (const float*)d_in[0];
    const int*   qw   = (const int*)d_in[1];
    const float* sc   = (const float*)d_in[2];
    const float* bias = (const float*)d_in[3];
    float* out = (float*)d_out;

    static cudaStream_t s2 = nullptr;
    static cudaEvent_t eFork = nullptr, eJoin = nullptr;
    if (!s2) {
        cudaStreamCreateWithFlags(&s2, cudaStreamNonBlocking);
        cudaEventCreateWithFlags(&eFork, cudaEventDisableTiming);
        cudaEventCreateWithFlags(&eJoin, cudaEventDisableTiming);
    }

    cudaFuncSetAttribute(gemm_k, cudaFuncAttributeMaxDynamicSharedMemorySize, SMEM_BYTES);

    cudaEventRecord(eFork, 0);
    cudaStreamWaitEvent(s2, eFork, 0);
    round_a_k<<<(int)((size_t)Mdim * Kdim / 8 / 256), 256, 0, s2>>>((const float4*)inp);
    cudaEventRecord(eJoin, s2);

    dequant_k<<<dim3(Ndim / 32, Kdim / 64), 256>>>(qw, sc);

    cudaStreamWaitEvent(0, eJoin, 0);
    gemm_k<<<dim3(Ndim / NT, Mdim / MT), 128, SMEM_BYTES>>>(bias, out);
}